// round 11
// baseline (speedup 1.0000x reference)
#include <cuda_runtime.h>
#include <cstdint>

// RollerPooling forward — 4 rows per warp, all loads front-batched (4x
// LDG.128 + 4x LDG.32 in flight), registers capped via launch_bounds(256,6)
// so MLP=4 coexists with 75% occupancy (R5 had this MLP at only 62% occ).
// Streaming cache ops, zero shared memory.
// out[e][j] = (csum[min(j+w,128)] - csum[j]) / w,  w = 129 - target_size[e].
// Per row: warp shuffle scan -> shuffle gather (w warp-uniform: index
// 4*lane+k+w lives in register c_{(k+b)&3} of lane lane+q+carry, w=4q+b).

#define N_CH 128
#define WARPS_PER_BLOCK 8
#define THREADS (WARPS_PER_BLOCK * 32)
#define CTAS_PER_SM 6
#define ROWS_PER_WARP 4

__device__ __forceinline__ float4 roller_row(float4 v, int w, int lane) {
    const unsigned m = 0xffffffffu;

    // Lane sum + inclusive warp scan of lane sums.
    float s = v.x + v.y + v.z + v.w;
    float inc = s;
    #pragma unroll
    for (int o = 1; o < 32; o <<= 1) {
        float t = __shfl_up_sync(m, inc, o);
        if (lane >= o) inc += t;
    }
    const float excl = inc - s;

    // Exclusive csum at this lane's 4 elements (registers only).
    const float c0 = excl;
    const float c1 = c0 + v.x;
    const float c2 = c1 + v.y;
    const float c3 = c2 + v.z;

    const float total = __shfl_sync(m, inc, 31);   // csum[128]

    const int q = w >> 2;
    const int b = w & 3;
    const float invw = 1.0f / (float)w;

    // Gather csum[4*lane + k + w] via shuffles (srcLane = (4*lane+k+w)>>2;
    // mod-32 wrap for OOB lanes is overridden by the clamp below).
    const float g0 = __shfl_sync(m, c0, lane + q + (0 < b ? 1 : 0));
    const float g1 = __shfl_sync(m, c1, lane + q + (1 < b ? 1 : 0));
    const float g2 = __shfl_sync(m, c2, lane + q + (2 < b ? 1 : 0));
    const float g3 = __shfl_sync(m, c3, lane + q + (3 < b ? 1 : 0));

    // Permute: end-of-window csum for output k uses residue (k+b)&3.
    float e0, e1, e2, e3;
    switch (b) {   // warp-uniform branch
        case 0:  e0 = g0; e1 = g1; e2 = g2; e3 = g3; break;
        case 1:  e0 = g1; e1 = g2; e2 = g3; e3 = g0; break;
        case 2:  e0 = g2; e1 = g3; e2 = g0; e3 = g1; break;
        default: e0 = g3; e1 = g0; e2 = g1; e3 = g2; break;
    }

    // Clamp: window ends past 128 read csum[128] = total.
    const int j = lane << 2;
    if (j + 0 + w >= N_CH) e0 = total;
    if (j + 1 + w >= N_CH) e1 = total;
    if (j + 2 + w >= N_CH) e2 = total;
    if (j + 3 + w >= N_CH) e3 = total;

    float4 o4;
    o4.x = (e0 - c0) * invw;
    o4.y = (e1 - c1) * invw;
    o4.z = (e2 - c2) * invw;
    o4.w = (e3 - c3) * invw;
    return o4;
}

__global__ __launch_bounds__(THREADS, CTAS_PER_SM)
void roller_pooling_kernel(const float* __restrict__ hidden,
                           const int* __restrict__ target_size,
                           float* __restrict__ out,
                           int n_edges) {
    const int warp = threadIdx.x >> 5;
    const int lane = threadIdx.x & 31;
    const int base = (blockIdx.x * WARPS_PER_BLOCK + warp) * ROWS_PER_WARP;
    if (base >= n_edges) return;

    // Branch-free row clamping: rows past the end recompute the last valid
    // row (identical inputs -> identical double-write; deterministic).
    int e[ROWS_PER_WARP];
    #pragma unroll
    for (int r = 0; r < ROWS_PER_WARP; r++)
        e[r] = min(base + r, n_edges - 1);

    // Front-batch ALL global loads: 4x LDG.128 + 4x LDG.32 in flight
    // before any dependent compute. Streaming (zero reuse).
    float4 v[ROWS_PER_WARP];
    #pragma unroll
    for (int r = 0; r < ROWS_PER_WARP; r++)
        v[r] = __ldcs(reinterpret_cast<const float4*>(hidden + (size_t)e[r] * N_CH) + lane);

    int ts[ROWS_PER_WARP];
    #pragma unroll
    for (int r = 0; r < ROWS_PER_WARP; r++)
        ts[r] = __ldcs(target_size + e[r]);

    #pragma unroll
    for (int r = 0; r < ROWS_PER_WARP; r++) {
        float4 o = roller_row(v[r], (N_CH + 1) - ts[r], lane);
        __stcs(reinterpret_cast<float4*>(out + (size_t)e[r] * N_CH) + lane, o);
    }
}

extern "C" void kernel_launch(void* const* d_in, const int* in_sizes, int n_in,
                              void* d_out, int out_size) {
    const float* hidden = (const float*)d_in[0];
    const int* target_size = (const int*)d_in[1];
    float* out = (float*)d_out;
    const int n_edges = in_sizes[1];

    const int rows_per_block = WARPS_PER_BLOCK * ROWS_PER_WARP;
    const int blocks = (n_edges + rows_per_block - 1) / rows_per_block;
    roller_pooling_kernel<<<blocks, THREADS>>>(hidden, target_size, out, n_edges);
}

// round 12
// speedup vs baseline: 1.0149x; 1.0149x over previous
#include <cuda_runtime.h>
#include <cstdint>

// RollerPooling forward — final/champion kernel.
// 16 warps/block, 2 rows per warp, regs 31 / occ ~80%, streaming cache ops,
// zero shared memory, branch-free tail handling.
//
// out[e][j] = (csum[min(j+w,128)] - csum[j]) / w,  w = 129 - target_size[e].
// Per row: float4 coalesced load -> warp shuffle scan -> register-only
// exclusive csum -> shuffle-based gather (w is warp-uniform: index 4*lane+k+w
// lives in register c_{(k+b)&3} of lane lane+q+carry, where w=4q+b) ->
// float4 coalesced store.
//
// Measured at the chip's mixed-read/write HBM ceiling (~6.3-6.4 TB/s, ~80%
// of spec): traffic is irreducible (514 MB, zero reuse, fully coalesced),
// so this sits at the roofline for the problem.

#define N_CH 128
#define WARPS_PER_BLOCK 16
#define THREADS (WARPS_PER_BLOCK * 32)

__device__ __forceinline__ float4 roller_row(float4 v, int w, int lane) {
    const unsigned m = 0xffffffffu;

    // Lane sum + inclusive warp scan of lane sums.
    float s = v.x + v.y + v.z + v.w;
    float inc = s;
    #pragma unroll
    for (int o = 1; o < 32; o <<= 1) {
        float t = __shfl_up_sync(m, inc, o);
        if (lane >= o) inc += t;
    }
    const float excl = inc - s;

    // Exclusive csum at this lane's 4 elements (registers only).
    const float c0 = excl;
    const float c1 = c0 + v.x;
    const float c2 = c1 + v.y;
    const float c3 = c2 + v.z;

    const float total = __shfl_sync(m, inc, 31);   // csum[128]

    const int q = w >> 2;
    const int b = w & 3;
    const float invw = 1.0f / (float)w;

    // Gather csum[4*lane + k + w] via shuffles (srcLane = (4*lane+k+w)>>2;
    // mod-32 wrap for OOB lanes is overridden by the clamp below).
    const float g0 = __shfl_sync(m, c0, lane + q + (0 < b ? 1 : 0));
    const float g1 = __shfl_sync(m, c1, lane + q + (1 < b ? 1 : 0));
    const float g2 = __shfl_sync(m, c2, lane + q + (2 < b ? 1 : 0));
    const float g3 = __shfl_sync(m, c3, lane + q + (3 < b ? 1 : 0));

    // Permute: end-of-window csum for output k uses residue (k+b)&3.
    float e0, e1, e2, e3;
    switch (b) {   // warp-uniform branch
        case 0:  e0 = g0; e1 = g1; e2 = g2; e3 = g3; break;
        case 1:  e0 = g1; e1 = g2; e2 = g3; e3 = g0; break;
        case 2:  e0 = g2; e1 = g3; e2 = g0; e3 = g1; break;
        default: e0 = g3; e1 = g0; e2 = g1; e3 = g2; break;
    }

    // Clamp: window ends past 128 read csum[128] = total.
    const int j = lane << 2;
    if (j + 0 + w >= N_CH) e0 = total;
    if (j + 1 + w >= N_CH) e1 = total;
    if (j + 2 + w >= N_CH) e2 = total;
    if (j + 3 + w >= N_CH) e3 = total;

    float4 o4;
    o4.x = (e0 - c0) * invw;
    o4.y = (e1 - c1) * invw;
    o4.z = (e2 - c2) * invw;
    o4.w = (e3 - c3) * invw;
    return o4;
}

__global__ __launch_bounds__(THREADS)
void roller_pooling_kernel(const float* __restrict__ hidden,
                           const int* __restrict__ target_size,
                           float* __restrict__ out,
                           int n_edges) {
    const int warp = threadIdx.x >> 5;
    const int lane = threadIdx.x & 31;
    const int eA = (blockIdx.x * WARPS_PER_BLOCK + warp) * 2;
    if (eA >= n_edges) return;

    // Branch-free second row: clamp to last valid row. If clamped, row B
    // recomputes row A from identical inputs -> identical double-write.
    const int eB = min(eA + 1, n_edges - 1);

    // Front-batched streaming loads (2x LDG.128 + 2x LDG.32 in flight).
    float4 vA = __ldcs(reinterpret_cast<const float4*>(hidden + (size_t)eA * N_CH) + lane);
    float4 vB = __ldcs(reinterpret_cast<const float4*>(hidden + (size_t)eB * N_CH) + lane);
    const int tsA = __ldcs(target_size + eA);
    const int tsB = __ldcs(target_size + eB);

    float4 oA = roller_row(vA, (N_CH + 1) - tsA, lane);
    __stcs(reinterpret_cast<float4*>(out + (size_t)eA * N_CH) + lane, oA);

    float4 oB = roller_row(vB, (N_CH + 1) - tsB, lane);
    __stcs(reinterpret_cast<float4*>(out + (size_t)eB * N_CH) + lane, oB);
}

extern "C" void kernel_launch(void* const* d_in, const int* in_sizes, int n_in,
                              void* d_out, int out_size) {
    const float* hidden = (const float*)d_in[0];
    const int* target_size = (const int*)d_in[1];
    float* out = (float*)d_out;
    const int n_edges = in_sizes[1];

    const int rows_per_block = WARPS_PER_BLOCK * 2;
    const int blocks = (n_edges + rows_per_block - 1) / rows_per_block;
    roller_pooling_kernel<<<blocks, THREADS>>>(hidden, target_size, out, n_edges);
}